// round 4
// baseline (speedup 1.0000x reference)
#include <cuda_runtime.h>

// x: [32, 28, 28, 512] fp32 (only batch 0 used); out: [32, 29, 29, 1] fp32.
#define HH    28
#define WW    28
#define CC    512
#define NPOS  (HH * WW)      // 784
#define OD    29
#define OUT2D (OD * OD)      // 841
#define BATCH 32
#define NCTA  49             // 16 warps/CTA * 49 = 784 positions
#define NTHREADS 512
#define NTAILSKIP (NCTA - BATCH)   // first 17 arrivals exit

__device__ float        g_fsq[NPOS];
__device__ unsigned int g_count = 0;   // phase-1 arrivals
__device__ unsigned int g_done  = 0;   // tail spin-exits (for reset election)

__global__ void __launch_bounds__(NTHREADS)
fused_kernel(const float* __restrict__ x, float* __restrict__ out) {
    const int tid  = threadIdx.x;
    const int wid  = tid >> 5;
    const int lane = tid & 31;
    const int p    = blockIdx.x * 16 + wid;   // 0..783, one warp per position

    __shared__ unsigned int order_s;
    __shared__ unsigned int done_s;

    // ---------------- Phase 1: fsq[p] = sum_c x[0,p,c]^2 (one warp/pos) ----
    {
        const float4* xp = reinterpret_cast<const float4*>(x + (size_t)p * CC);
        float s = 0.f;
        #pragma unroll
        for (int k = 0; k < 4; ++k) {          // 128 float4 per position / 32 lanes
            const float4 v = xp[k * 32 + lane];
            s += v.x * v.x + v.y * v.y + v.z * v.z + v.w * v.w;
        }
        #pragma unroll
        for (int o = 16; o > 0; o >>= 1)
            s += __shfl_xor_sync(0xffffffffu, s, o);
        if (lane == 0)
            g_fsq[p] = s;
    }
    __syncthreads();

    if (tid == 0) {
        __threadfence();                       // release g_fsq writes
        order_s = atomicAdd(&g_count, 1u);     // arrival order (49 atomics total)
    }
    __syncthreads();

    const unsigned int order = order_s;
    if (order < (unsigned int)NTAILSKIP) return;   // 17 CTAs exit now

    // ---------------- Phase 2: last 32 arrivals, one batch element each ----
    const int b = (int)order - NTAILSKIP;

    if (tid == 0) {
        // All 49 CTAs are trivially co-resident -> spin cannot deadlock.
        volatile unsigned int* vc = &g_count;
        while (*vc != (unsigned int)NCTA) { }
        done_s = atomicAdd(&g_done, 1u);
    }
    __syncthreads();
    __threadfence();                           // acquire g_fsq

    __shared__ float fsq_s[NPOS];
    __shared__ float I[OD][OD + 3];            // pad vs bank conflicts

    #pragma unroll
    for (int k = tid; k < NPOS; k += NTHREADS)
        fsq_s[k] = __ldcg(&g_fsq[k]);

    if (tid < OD) { I[tid][0] = 0.f; I[0][tid] = 0.f; }
    __syncthreads();

    // Row cumsums (28 threads, FADD chain in a register).
    if (tid < HH) {
        float run = 0.f;
        #pragma unroll
        for (int c = 0; c < WW; ++c) {
            run += fsq_s[tid * WW + c];
            I[tid + 1][c + 1] = run;
        }
    }
    __syncthreads();

    // Column cumsums (28 threads; loads independent, pipeline under FADD chain).
    if (tid < WW) {
        const int c = tid + 1;
        float run = 0.f;
        #pragma unroll
        for (int r = 1; r <= HH; ++r) {
            run += I[r][c];
            I[r][c] = run;
        }
    }
    __syncthreads();

    // Box sums -> this block's batch slice (2 iterations per thread).
    float* ob = out + (size_t)b * OUT2D;
    #pragma unroll
    for (int k = tid; k < OUT2D; k += NTHREADS) {
        const int i = k / OD, j = k - i * OD;
        const int r0 = min(max(HH / 2 - i, 0), HH);
        const int r1 = min(max(HH / 2 + HH - i, 0), HH);
        const int c0 = min(max(WW / 2 - j, 0), WW);
        const int c1 = min(max(WW / 2 + WW - j, 0), WW);
        ob[k] = I[r1][c1] - I[r0][c1] - I[r1][c0] + I[r0][c0];
    }

    // Last spin-exiter resets both counters for the next graph replay.
    if (tid == 0 && done_s == (unsigned int)(BATCH - 1)) {
        g_done  = 0;
        __threadfence();
        g_count = 0;
    }
}

extern "C" void kernel_launch(void* const* d_in, const int* in_sizes, int n_in,
                              void* d_out, int out_size) {
    const float* x = (const float*)d_in[0];
    float* out     = (float*)d_out;
    fused_kernel<<<NCTA, NTHREADS>>>(x, out);
}